// round 2
// baseline (speedup 1.0000x reference)
#include <cuda_runtime.h>
#include <cstdint>
#include <cstddef>

#define BATCH  4096
#define INDIM  1024
#define DICT   16384
#define KHALF  32
#define MAXSEL 64

// ---------------- compact selection scratch (static __device__, no allocs) ---
__device__ int   g_nsel[BATCH];
__device__ int   g_idx [BATCH * MAXSEL];
__device__ float g_hu  [BATCH * MAXSEL];
__device__ float g_hc  [BATCH * MAXSEL];

// =====================================================================
// Encoder GEMM: C[M,N] = A[M,K] * B[K,N] + bias[N]
// M=4096, K=1024, N=16384.  fp32 CUDA-core, 128x128x16 tiles, 8x8/thread,
// double-buffered smem. Baseline for correctness; tensor-core split-precision
// comes in a later round.
// =====================================================================
#define BM  128
#define BN  128
#define BKK 16

__global__ void __launch_bounds__(256, 2)
sgemm_bias(const float* __restrict__ A, const float* __restrict__ B,
           const float* __restrict__ bias, float* __restrict__ C)
{
    const int K = INDIM, N = DICT;
    __shared__ float As[2][BKK][BM];
    __shared__ float Bs[2][BKK][BN];

    const int tid = threadIdx.x;
    const int tx  = tid & 15;
    const int ty  = tid >> 4;
    const int m0  = blockIdx.y * BM;
    const int n0  = blockIdx.x * BN;

    const float* Ab = A + (size_t)m0 * K;
    const float* Bb = B + n0;

    // per-thread load coordinates (each thread moves 2 float4 of A, 2 of B)
    const int aR = tid >> 2;            // 0..63 (second chunk: +64)
    const int aK = (tid & 3) << 2;      // 0,4,8,12
    const int bK = tid >> 5;            // 0..7  (second chunk: +8)
    const int bN = (tid & 31) << 2;     // 0..124

    float acc[8][8];
    #pragma unroll
    for (int i = 0; i < 8; i++)
        #pragma unroll
        for (int j = 0; j < 8; j++) acc[i][j] = 0.0f;

    // ---- prologue: tile 0 into buffer 0 ----
    {
        float4 a0 = *reinterpret_cast<const float4*>(Ab + (size_t)aR * K + aK);
        float4 a1 = *reinterpret_cast<const float4*>(Ab + (size_t)(aR + 64) * K + aK);
        float4 b0 = *reinterpret_cast<const float4*>(Bb + (size_t)bK * N + bN);
        float4 b1 = *reinterpret_cast<const float4*>(Bb + (size_t)(bK + 8) * N + bN);
        As[0][aK + 0][aR] = a0.x; As[0][aK + 1][aR] = a0.y;
        As[0][aK + 2][aR] = a0.z; As[0][aK + 3][aR] = a0.w;
        As[0][aK + 0][aR + 64] = a1.x; As[0][aK + 1][aR + 64] = a1.y;
        As[0][aK + 2][aR + 64] = a1.z; As[0][aK + 3][aR + 64] = a1.w;
        *reinterpret_cast<float4*>(&Bs[0][bK][bN])     = b0;
        *reinterpret_cast<float4*>(&Bs[0][bK + 8][bN]) = b1;
    }
    __syncthreads();

    const int nk = K / BKK;   // 64
    for (int t = 0; t < nk; t++) {
        const int buf = t & 1;
        float4 pa0, pa1, pb0, pb1;
        const bool more = (t + 1 < nk);
        if (more) {
            const int k0 = (t + 1) * BKK;
            pa0 = *reinterpret_cast<const float4*>(Ab + (size_t)aR * K + k0 + aK);
            pa1 = *reinterpret_cast<const float4*>(Ab + (size_t)(aR + 64) * K + k0 + aK);
            pb0 = *reinterpret_cast<const float4*>(Bb + (size_t)(k0 + bK) * N + bN);
            pb1 = *reinterpret_cast<const float4*>(Bb + (size_t)(k0 + bK + 8) * N + bN);
        }

        #pragma unroll
        for (int k = 0; k < BKK; k++) {
            float4 a0 = *reinterpret_cast<const float4*>(&As[buf][k][ty * 8]);
            float4 a1 = *reinterpret_cast<const float4*>(&As[buf][k][ty * 8 + 4]);
            float4 b0 = *reinterpret_cast<const float4*>(&Bs[buf][k][tx * 8]);
            float4 b1 = *reinterpret_cast<const float4*>(&Bs[buf][k][tx * 8 + 4]);
            float ra[8] = {a0.x, a0.y, a0.z, a0.w, a1.x, a1.y, a1.z, a1.w};
            float rb[8] = {b0.x, b0.y, b0.z, b0.w, b1.x, b1.y, b1.z, b1.w};
            #pragma unroll
            for (int i = 0; i < 8; i++)
                #pragma unroll
                for (int j = 0; j < 8; j++)
                    acc[i][j] += ra[i] * rb[j];
        }

        if (more) {
            const int wb = buf ^ 1;
            As[wb][aK + 0][aR] = pa0.x; As[wb][aK + 1][aR] = pa0.y;
            As[wb][aK + 2][aR] = pa0.z; As[wb][aK + 3][aR] = pa0.w;
            As[wb][aK + 0][aR + 64] = pa1.x; As[wb][aK + 1][aR + 64] = pa1.y;
            As[wb][aK + 2][aR + 64] = pa1.z; As[wb][aK + 3][aR + 64] = pa1.w;
            *reinterpret_cast<float4*>(&Bs[wb][bK][bN])     = pb0;
            *reinterpret_cast<float4*>(&Bs[wb][bK + 8][bN]) = pb1;
        }
        __syncthreads();
    }

    // ---- epilogue: C = acc + bias ----
    const float* bp = bias + n0 + tx * 8;
    float bb[8];
    #pragma unroll
    for (int j = 0; j < 8; j++) bb[j] = bp[j];
    #pragma unroll
    for (int i = 0; i < 8; i++) {
        const int row = m0 + ty * 8 + i;
        float* Cp = C + (size_t)row * N + n0 + tx * 8;
        float4 o0, o1;
        o0.x = acc[i][0] + bb[0]; o0.y = acc[i][1] + bb[1];
        o0.z = acc[i][2] + bb[2]; o0.w = acc[i][3] + bb[3];
        o1.x = acc[i][4] + bb[4]; o1.y = acc[i][5] + bb[5];
        o1.z = acc[i][6] + bb[6]; o1.w = acc[i][7] + bb[7];
        *reinterpret_cast<float4*>(Cp)     = o0;
        *reinterpret_cast<float4*>(Cp + 4) = o1;
    }
}

// =====================================================================
// Exact per-row top-32 via 8-bit radix select (monotone float->uint keys).
// Ties broken by smallest index (matches jax.lax.top_k stable ordering).
// =====================================================================
__device__ __forceinline__ unsigned fkey(float f)
{
    unsigned u = __float_as_uint(f);
    return (u & 0x80000000u) ? ~u : (u | 0x80000000u);
}

struct TopkShared {
    unsigned hist[256];
    int      ngt, neq;
    int      eqbuf[64];
    unsigned sprefix;
    int      sneed;
    int      ulist[KHALF];
    int      clist[KHALF];
    int      cnt;
};

__device__ void select_top32(const float* __restrict__ rowp, int* outlist, TopkShared* s)
{
    const int tid = threadIdx.x;
    unsigned prefix = 0, pmask = 0;
    int need = KHALF;

    for (int shift = 24; shift >= 0; shift -= 8) {
        s->hist[tid] = 0;
        __syncthreads();
        for (int i = tid; i < DICT; i += 256) {
            unsigned k = fkey(rowp[i]);
            if ((k & pmask) == prefix)
                atomicAdd(&s->hist[(k >> shift) & 255], 1u);
        }
        __syncthreads();
        if (tid == 0) {
            int cum = 0;
            int b = 255;
            for (; b > 0; b--) {
                int c = (int)s->hist[b];
                if (cum + c >= need) break;
                cum += c;
            }
            s->sprefix = prefix | ((unsigned)b << shift);
            s->sneed   = need - cum;
        }
        __syncthreads();
        prefix = s->sprefix;
        need   = s->sneed;
        pmask |= (0xFFu << shift);
        __syncthreads();
    }

    // prefix == key of the 32nd-largest; take (KHALF-need) strictly-greater
    // plus `need` equal keys at smallest indices.
    if (tid == 0) { s->ngt = 0; s->neq = 0; }
    __syncthreads();
    const unsigned thr = prefix;
    for (int i = tid; i < DICT; i += 256) {
        unsigned k = fkey(rowp[i]);
        if (k > thr) {
            int p = atomicAdd(&s->ngt, 1);
            outlist[p] = i;
        } else if (k == thr) {
            int p = atomicAdd(&s->neq, 1);
            if (p < 64) s->eqbuf[p] = i;
        }
    }
    __syncthreads();
    if (tid == 0) {
        int base = s->ngt;                    // == KHALF - need
        int ne = s->neq; if (ne > 64) ne = 64;
        for (int a = 1; a < ne; a++) {        // ascending insertion sort (tiny)
            int v = s->eqbuf[a]; int b = a - 1;
            while (b >= 0 && s->eqbuf[b] > v) { s->eqbuf[b + 1] = s->eqbuf[b]; b--; }
            s->eqbuf[b + 1] = v;
        }
        for (int q = 0; q < need; q++) outlist[base + q] = s->eqbuf[q];
    }
    __syncthreads();
}

__global__ void __launch_bounds__(256)
topk_kernel(const float* __restrict__ Hu, const float* __restrict__ Hc)
{
    __shared__ TopkShared s;
    const int row = blockIdx.x;
    const int tid = threadIdx.x;
    const float* ru = Hu + (size_t)row * DICT;
    const float* rc = Hc + (size_t)row * DICT;

    select_top32(ru, s.ulist, &s);
    select_top32(rc, s.clist, &s);

    if (tid == 0) s.cnt = KHALF;
    __syncthreads();

    if (tid < KHALF) {
        int idx = s.ulist[tid];
        g_idx[row * MAXSEL + tid] = idx;
        g_hu [row * MAXSEL + tid] = ru[idx];
        g_hc [row * MAXSEL + tid] = rc[idx];
    }
    if (tid < KHALF) {
        int idx = s.clist[tid];
        bool dup = false;
        for (int q = 0; q < KHALF; q++) dup |= (s.ulist[q] == idx);
        if (!dup) {
            int p = atomicAdd(&s.cnt, 1);
            g_idx[row * MAXSEL + p] = idx;
            g_hu [row * MAXSEL + p] = ru[idx];
            g_hc [row * MAXSEL + p] = rc[idx];
        }
    }
    __syncthreads();
    if (tid == 0) g_nsel[row] = s.cnt;
}

// =====================================================================
// zero-fill z_u / z_c / mask (contiguous region), then scatter selected.
// =====================================================================
__global__ void fill_zero(float4* __restrict__ p, size_t n4)
{
    size_t i = (size_t)blockIdx.x * blockDim.x + threadIdx.x;
    size_t stride = (size_t)gridDim.x * blockDim.x;
    float4 z = make_float4(0.f, 0.f, 0.f, 0.f);
    for (; i < n4; i += stride) p[i] = z;
}

__global__ void scatter_kernel(float* __restrict__ zu, float* __restrict__ zc,
                               float* __restrict__ mk)
{
    const int row = blockIdx.x;
    const int s   = threadIdx.x;
    if (s < g_nsel[row]) {
        const int idx = g_idx[row * MAXSEL + s];
        const size_t o = (size_t)row * DICT + idx;
        mk[o] = 1.0f;
        zu[o] = fmaxf(g_hu[row * MAXSEL + s], 0.f);
        zc[o] = fmaxf(g_hc[row * MAXSEL + s], 0.f);
    }
}

// =====================================================================
// Sparse decode: per row, gather <=64 W_dec rows once, produce both the
// "same" and "cross" outputs for that decoder.
//   A_is_u=1: Wd=W_dec_u, outA=x_u_hat (coef z_u), outB=x_u_cross (coef z_c)
//   A_is_u=0: Wd=W_dec_c, outA=x_c_hat (coef z_c), outB=x_c_cross (coef z_u)
// =====================================================================
__global__ void __launch_bounds__(256)
decode_kernel(const float* __restrict__ Wd, float* __restrict__ outA,
              float* __restrict__ outB, int A_is_u)
{
    __shared__ int   sn;
    __shared__ int   sidx[MAXSEL];
    __shared__ float ca[MAXSEL], cb[MAXSEL];
    const int row = blockIdx.x;
    const int tid = threadIdx.x;

    if (tid == 0) sn = g_nsel[row];
    if (tid < MAXSEL) {
        sidx[tid] = g_idx[row * MAXSEL + tid];
        float zu = fmaxf(g_hu[row * MAXSEL + tid], 0.f);
        float zc = fmaxf(g_hc[row * MAXSEL + tid], 0.f);
        ca[tid] = A_is_u ? zu : zc;
        cb[tid] = A_is_u ? zc : zu;
    }
    __syncthreads();

    float4 a = make_float4(0.f, 0.f, 0.f, 0.f);
    float4 b = make_float4(0.f, 0.f, 0.f, 0.f);
    const int n = sn;
    #pragma unroll 4
    for (int s = 0; s < n; s++) {
        const float4 w = *reinterpret_cast<const float4*>(
            Wd + (size_t)sidx[s] * INDIM + tid * 4);
        const float fa = ca[s], fb = cb[s];
        a.x += fa * w.x; a.y += fa * w.y; a.z += fa * w.z; a.w += fa * w.w;
        b.x += fb * w.x; b.y += fb * w.y; b.z += fb * w.z; b.w += fb * w.w;
    }
    const size_t o = (size_t)row * INDIM + tid * 4;
    *reinterpret_cast<float4*>(outA + o) = a;
    *reinterpret_cast<float4*>(outB + o) = b;
}

// =====================================================================
// launch
// =====================================================================
extern "C" void kernel_launch(void* const* d_in, const int* in_sizes, int n_in,
                              void* d_out, int out_size)
{
    const float* x_u     = (const float*)d_in[0];
    const float* x_c     = (const float*)d_in[1];
    const float* W_enc_u = (const float*)d_in[2];
    const float* b_enc_u = (const float*)d_in[3];
    const float* W_enc_c = (const float*)d_in[4];
    const float* b_enc_c = (const float*)d_in[5];
    const float* W_dec_u = (const float*)d_in[6];
    const float* W_dec_c = (const float*)d_in[7];

    float* out = (float*)d_out;
    const size_t ZN = (size_t)BATCH * DICT;       // 67,108,864
    const size_t XN = (size_t)BATCH * INDIM;      //  4,194,304
    float* z_u  = out;
    float* z_c  = out + ZN;
    float* mk   = out + 2 * ZN;
    float* xuh  = out + 3 * ZN;
    float* xch  = xuh + XN;
    float* xuc  = xch + XN;
    float* xcc  = xuc + XN;

    dim3 gemm_grid(DICT / BN, BATCH / BM);        // 128 x 32

    // h_u / h_c are staged in the z_u / z_c output regions (read by topk,
    // then overwritten by fill+scatter).
    sgemm_bias<<<gemm_grid, 256>>>(x_u, W_enc_u, b_enc_u, z_u);
    sgemm_bias<<<gemm_grid, 256>>>(x_c, W_enc_c, b_enc_c, z_c);

    topk_kernel<<<BATCH, 256>>>(z_u, z_c);

    fill_zero<<<8192, 256>>>((float4*)out, (3 * ZN) / 4);

    scatter_kernel<<<BATCH, MAXSEL>>>(z_u, z_c, mk);

    decode_kernel<<<BATCH, 256>>>(W_dec_u, xuh, xuc, 1);
    decode_kernel<<<BATCH, 256>>>(W_dec_c, xch, xcc, 0);
}

// round 4
// speedup vs baseline: 3.3331x; 3.3331x over previous
#include <cuda_runtime.h>
#include <cuda_bf16.h>
#include <cstdint>
#include <cstddef>

#define BATCH   4096
#define INDIM   1024
#define DICT    16384
#define KHALF   32
#define MAXSEL  64
#define CANDMAX 128
#define MARGIN  0.02f

// ---------------- __device__ scratch (no allocs) ----------------------------
__device__ __nv_bfloat16 g_xb [2][(size_t)BATCH * INDIM];
__device__ __nv_bfloat16 g_Wtb[2][(size_t)DICT * INDIM];   // W^T bf16 [N,K]
__device__ float         g_Wt [2][(size_t)DICT * INDIM];   // W^T fp32 [N,K]
__device__ int   g_cn [2][BATCH];
__device__ int   g_ci [2][BATCH][CANDMAX];
__device__ int   g_nsel[BATCH];
__device__ int   g_idx [BATCH * MAXSEL];
__device__ float g_hu  [BATCH * MAXSEL];
__device__ float g_hc  [BATCH * MAXSEL];

// ---------------- PTX helpers (sm_80-era only!) -----------------------------
__device__ __forceinline__ uint32_t smem_u32(const void* p) {
    uint32_t a;
    asm("{ .reg .u64 t; cvta.to.shared.u64 t, %1; cvt.u32.u64 %0, t; }" : "=r"(a) : "l"(p));
    return a;
}
__device__ __forceinline__ void cpa16(uint32_t s, const void* g) {
    asm volatile("cp.async.cg.shared.global [%0], [%1], 16;" :: "r"(s), "l"(g));
}
__device__ __forceinline__ void cpa_commit() { asm volatile("cp.async.commit_group;" ::: "memory"); }
__device__ __forceinline__ void cpa_wait2()  { asm volatile("cp.async.wait_group 2;" ::: "memory"); }

__device__ __forceinline__ void ldsm4(uint32_t* r, uint32_t addr) {
    asm volatile("ldmatrix.sync.aligned.m8n8.x4.shared.b16 {%0,%1,%2,%3}, [%4];"
        : "=r"(r[0]), "=r"(r[1]), "=r"(r[2]), "=r"(r[3]) : "r"(addr));
}
__device__ __forceinline__ void mma16816(float* d, const uint32_t* a, const uint32_t* b) {
    asm volatile("mma.sync.aligned.m16n8k16.row.col.f32.bf16.bf16.f32 "
        "{%0,%1,%2,%3}, {%4,%5,%6,%7}, {%8,%9}, {%0,%1,%2,%3};"
        : "+f"(d[0]), "+f"(d[1]), "+f"(d[2]), "+f"(d[3])
        : "r"(a[0]), "r"(a[1]), "r"(a[2]), "r"(a[3]), "r"(b[0]), "r"(b[1]));
}

// ---------------- preprocessing ---------------------------------------------
__global__ void conv_x(const float* __restrict__ x, int enc)
{
    size_t n = (size_t)BATCH * INDIM;
    for (size_t i = (size_t)blockIdx.x * blockDim.x + threadIdx.x; i < n;
         i += (size_t)gridDim.x * blockDim.x)
        g_xb[enc][i] = __float2bfloat16_rn(x[i]);
}

// W [K,N] -> W^T fp32 + bf16 [N,K]
__global__ void trans_w(const float* __restrict__ W, int enc)
{
    __shared__ float t[32][33];
    const int n0 = blockIdx.x * 32, k0 = blockIdx.y * 32;
    const int tx = threadIdx.x, ty = threadIdx.y;
    #pragma unroll
    for (int j = 0; j < 4; j++)
        t[ty + j * 8][tx] = W[(size_t)(k0 + ty + j * 8) * DICT + n0 + tx];
    __syncthreads();
    #pragma unroll
    for (int j = 0; j < 4; j++) {
        float v = t[tx][ty + j * 8];
        size_t o = (size_t)(n0 + ty + j * 8) * INDIM + k0 + tx;
        g_Wt [enc][o] = v;
        g_Wtb[enc][o] = __float2bfloat16_rn(v);
    }
}

// ---------------- bf16 mma.sync GEMM ----------------------------------------
// h~[4096,16384] = x_bf16 @ W_bf16 + bias.  BM=128 BN=128 BK=32, 3-stage
// cp.async, 8 warps (2M x 4N), warp tile 64x32, mma m16n8k16.
#define GBM 128
#define GBN 128
#define GBK 32
#define GROWB 40            // padded bf16 row (80 B) -> conflict-free ldmatrix
#define GSTB  20480         // bytes per stage (A 10240 + B 10240)
#define GST   3
#define GEMM_SMEM (GST * GSTB)
#define NKI (INDIM / GBK)   // 32

__device__ __forceinline__ void g_load(uint32_t sbase,
    const __nv_bfloat16* __restrict__ Xb, const __nv_bfloat16* __restrict__ Wb,
    int m0, int n0, int k0, int tid)
{
    #pragma unroll
    for (int r = 0; r < 2; r++) {
        int i = tid + r * 256;
        int row = i >> 2, c = i & 3;
        cpa16(sbase + row * 80 + c * 16,
              Xb + (size_t)(m0 + row) * INDIM + k0 + c * 8);
        cpa16(sbase + 10240 + row * 80 + c * 16,
              Wb + (size_t)(n0 + row) * INDIM + k0 + c * 8);
    }
}

__global__ void __launch_bounds__(256, 2)
gemm_bf16(int enc, const float* __restrict__ bias, float* __restrict__ C)
{
    extern __shared__ __align__(128) char sm[];
    __shared__ float s_bias[GBN];
    const uint32_t sb = smem_u32(sm);
    const int tid = threadIdx.x, lane = tid & 31, wid = tid >> 5;
    const int wm = wid & 1, wn = wid >> 1;          // 2 x 4 warps
    const int m0 = blockIdx.x * GBM;                // x fast => B-panel L2 reuse
    const int n0 = blockIdx.y * GBN;

    const __nv_bfloat16* Xb = g_xb [enc];
    const __nv_bfloat16* Wb = g_Wtb[enc];

    if (tid < GBN) s_bias[tid] = bias[n0 + tid];

    #pragma unroll
    for (int p = 0; p < GST; p++) {
        g_load(sb + p * GSTB, Xb, Wb, m0, n0, p * GBK, tid);
        cpa_commit();
    }

    float acc[4][4][4];
    #pragma unroll
    for (int a = 0; a < 4; a++)
        #pragma unroll
        for (int b = 0; b < 4; b++)
            #pragma unroll
            for (int c = 0; c < 4; c++) acc[a][b][c] = 0.f;

    for (int t = 0; t < NKI; t++) {
        const int s = t - (t / 3) * 3;
        const uint32_t sA = sb + s * GSTB, sB = sA + 10240;

        cpa_wait2();
        __syncthreads();

        #pragma unroll
        for (int ks = 0; ks < GBK; ks += 16) {
            uint32_t af[4][4], bf[4][2];
            #pragma unroll
            for (int mi = 0; mi < 4; mi++) {
                uint32_t addr = sA +
                    ((wm * 64 + mi * 16 + (lane & 15)) * GROWB + ks + ((lane >> 4) << 3)) * 2;
                ldsm4(af[mi], addr);
            }
            #pragma unroll
            for (int h = 0; h < 2; h++) {
                uint32_t r[4];
                uint32_t addr = sB +
                    ((wn * 32 + h * 16 + (lane & 7) + ((lane >> 4) << 3)) * GROWB
                     + ks + (((lane >> 3) & 1) << 3)) * 2;
                ldsm4(r, addr);
                bf[h * 2][0] = r[0]; bf[h * 2][1] = r[1];
                bf[h * 2 + 1][0] = r[2]; bf[h * 2 + 1][1] = r[3];
            }
            #pragma unroll
            for (int mi = 0; mi < 4; mi++)
                #pragma unroll
                for (int ni = 0; ni < 4; ni++)
                    mma16816(acc[mi][ni], af[mi], bf[ni]);
        }
        __syncthreads();

        if (t + GST < NKI)
            g_load(sb + s * GSTB, Xb, Wb, m0, n0, (t + GST) * GBK, tid);
        cpa_commit();
    }

    #pragma unroll
    for (int mi = 0; mi < 4; mi++) {
        const int rbase = m0 + wm * 64 + mi * 16 + (lane >> 2);
        #pragma unroll
        for (int ni = 0; ni < 4; ni++) {
            const int col = n0 + wn * 32 + ni * 8 + (lane & 3) * 2;
            const float b0 = s_bias[col - n0], b1 = s_bias[col - n0 + 1];
            float2 v0 = make_float2(acc[mi][ni][0] + b0, acc[mi][ni][1] + b1);
            float2 v1 = make_float2(acc[mi][ni][2] + b0, acc[mi][ni][3] + b1);
            *reinterpret_cast<float2*>(C + (size_t)rbase * DICT + col) = v0;
            *reinterpret_cast<float2*>(C + (size_t)(rbase + 8) * DICT + col) = v1;
        }
    }
}

// ---------------- threshold + candidate collection ---------------------------
__device__ __forceinline__ unsigned fkey(float f)
{
    unsigned u = __float_as_uint(f);
    return (u & 0x80000000u) ? ~u : (u | 0x80000000u);
}
__device__ __forceinline__ float key2f(unsigned k)
{
    unsigned u = (k & 0x80000000u) ? (k & 0x7FFFFFFFu) : ~k;
    return __uint_as_float(u);
}

__global__ void __launch_bounds__(256)
topcand(const float* __restrict__ Hu, const float* __restrict__ Hc)
{
    __shared__ unsigned hist[256];
    __shared__ unsigned sprefix;
    __shared__ int sneed, cnt;
    const int row = blockIdx.x, tid = threadIdx.x;

    for (int stream = 0; stream < 2; stream++) {
        const float* h = (stream ? Hc : Hu) + (size_t)row * DICT;
        unsigned prefix = 0, pmask = 0;
        int need = KHALF;

        for (int shift = 24; shift >= 0; shift -= 8) {
            hist[tid] = 0;
            __syncthreads();
            for (int i = tid; i < DICT; i += 256) {
                unsigned k = fkey(h[i]);
                if ((k & pmask) == prefix)
                    atomicAdd(&hist[(k >> shift) & 255], 1u);
            }
            __syncthreads();
            if (tid == 0) {
                int cum = 0, b = 255;
                for (; b > 0; b--) {
                    int c = (int)hist[b];
                    if (cum + c >= need) break;
                    cum += c;
                }
                sprefix = prefix | ((unsigned)b << shift);
                sneed   = need - cum;
            }
            __syncthreads();
            prefix = sprefix;
            need   = sneed;
            pmask |= (0xFFu << shift);
            __syncthreads();
        }

        const float cut = key2f(prefix) - MARGIN;
        if (tid == 0) cnt = 0;
        __syncthreads();
        for (int i = tid; i < DICT; i += 256) {
            if (h[i] > cut) {
                int p = atomicAdd(&cnt, 1);
                if (p < CANDMAX) g_ci[stream][row][p] = i;
            }
        }
        __syncthreads();
        if (tid == 0) g_cn[stream][row] = cnt < CANDMAX ? cnt : CANDMAX;
        __syncthreads();
    }
}

// ---------------- exact rescore + selection ---------------------------------
__global__ void __launch_bounds__(256)
rescore(const float* __restrict__ xu, const float* __restrict__ xc,
        const float* __restrict__ bu, const float* __restrict__ bc)
{
    __shared__ float sxu[INDIM], sxc[INDIM];
    __shared__ int   ci[2][CANDMAX];
    __shared__ float chu[2][CANDMAX], chc[2][CANDMAX];
    __shared__ int   nc[2];
    __shared__ int   selidx[2][KHALF];
    __shared__ float selhu[2][KHALF], selhc[2][KHALF];
    __shared__ int   cnt;

    const int row = blockIdx.x, tid = threadIdx.x;
    const int lane = tid & 31, wid = tid >> 5;

    for (int i = tid; i < INDIM; i += 256) {
        sxu[i] = xu[(size_t)row * INDIM + i];
        sxc[i] = xc[(size_t)row * INDIM + i];
    }
    if (tid < 2) nc[tid] = g_cn[tid][row];
    __syncthreads();
    for (int s = 0; s < 2; s++)
        for (int t = tid; t < nc[s]; t += 256) ci[s][t] = g_ci[s][row][t];
    __syncthreads();

    const int tot = nc[0] + nc[1];
    for (int t = wid; t < tot; t += 8) {
        const int s  = (t < nc[0]) ? 0 : 1;
        const int tt = (s == 0) ? t : t - nc[0];
        const int j  = ci[s][tt];
        const float* wu = g_Wt[0] + (size_t)j * INDIM;
        const float* wc = g_Wt[1] + (size_t)j * INDIM;
        float su = 0.f, sc2 = 0.f;
        for (int i = lane; i < INDIM; i += 32) {
            su  += sxu[i] * __ldg(wu + i);
            sc2 += sxc[i] * __ldg(wc + i);
        }
        #pragma unroll
        for (int o = 16; o > 0; o >>= 1) {
            su  += __shfl_down_sync(0xFFFFFFFFu, su,  o);
            sc2 += __shfl_down_sync(0xFFFFFFFFu, sc2, o);
        }
        if (lane == 0) {
            chu[s][tt] = su  + bu[j];
            chc[s][tt] = sc2 + bc[j];
        }
    }
    __syncthreads();

    // exact rank selection per stream: rank by (value desc, index asc)
    #pragma unroll
    for (int s = 0; s < 2; s++) {
        if (tid < nc[s]) {
            const float v = s ? chc[1][tid] : chu[0][tid];
            const int   j = ci[s][tid];
            int r = 0;
            for (int t2 = 0; t2 < nc[s]; t2++) {
                const float o = s ? chc[1][t2] : chu[0][t2];
                r += (o > v) || (o == v && ci[s][t2] < j);
            }
            if (r < KHALF) {
                selidx[s][r] = j;
                selhu[s][r]  = chu[s][tid];
                selhc[s][r]  = chc[s][tid];
            }
        }
    }
    __syncthreads();
    if (tid == 0) cnt = KHALF;
    __syncthreads();

    if (tid < KHALF) {
        g_idx[row * MAXSEL + tid] = selidx[0][tid];
        g_hu [row * MAXSEL + tid] = selhu[0][tid];
        g_hc [row * MAXSEL + tid] = selhc[0][tid];
    }
    if (tid < KHALF) {
        const int j = selidx[1][tid];
        bool dup = false;
        #pragma unroll
        for (int q = 0; q < KHALF; q++) dup |= (selidx[0][q] == j);
        if (!dup) {
            int p = atomicAdd(&cnt, 1);
            g_idx[row * MAXSEL + p] = j;
            g_hu [row * MAXSEL + p] = selhu[1][tid];
            g_hc [row * MAXSEL + p] = selhc[1][tid];
        }
    }
    __syncthreads();
    if (tid == 0) g_nsel[row] = cnt;
}

// ---------------- fill / scatter / decode -----------------------------------
__global__ void fill_zero(float4* __restrict__ p, size_t n4)
{
    size_t i = (size_t)blockIdx.x * blockDim.x + threadIdx.x;
    size_t stride = (size_t)gridDim.x * blockDim.x;
    float4 z = make_float4(0.f, 0.f, 0.f, 0.f);
    for (; i < n4; i += stride) p[i] = z;
}

__global__ void scatter_kernel(float* __restrict__ zu, float* __restrict__ zc,
                               float* __restrict__ mk)
{
    const int row = blockIdx.x;
    const int s   = threadIdx.x;
    if (s < g_nsel[row]) {
        const int idx = g_idx[row * MAXSEL + s];
        const size_t o = (size_t)row * DICT + idx;
        mk[o] = 1.0f;
        zu[o] = fmaxf(g_hu[row * MAXSEL + s], 0.f);
        zc[o] = fmaxf(g_hc[row * MAXSEL + s], 0.f);
    }
}

__global__ void __launch_bounds__(256)
decode_kernel(const float* __restrict__ Wd, float* __restrict__ outA,
              float* __restrict__ outB, int A_is_u)
{
    __shared__ int   sn;
    __shared__ int   sidx[MAXSEL];
    __shared__ float ca[MAXSEL], cb[MAXSEL];
    const int row = blockIdx.x;
    const int tid = threadIdx.x;

    if (tid == 0) sn = g_nsel[row];
    if (tid < MAXSEL) {
        sidx[tid] = g_idx[row * MAXSEL + tid];
        float zu = fmaxf(g_hu[row * MAXSEL + tid], 0.f);
        float zc = fmaxf(g_hc[row * MAXSEL + tid], 0.f);
        ca[tid] = A_is_u ? zu : zc;
        cb[tid] = A_is_u ? zc : zu;
    }
    __syncthreads();

    float4 a = make_float4(0.f, 0.f, 0.f, 0.f);
    float4 b = make_float4(0.f, 0.f, 0.f, 0.f);
    const int n = sn;
    #pragma unroll 4
    for (int s = 0; s < n; s++) {
        const float4 w = *reinterpret_cast<const float4*>(
            Wd + (size_t)sidx[s] * INDIM + tid * 4);
        const float fa = ca[s], fb = cb[s];
        a.x += fa * w.x; a.y += fa * w.y; a.z += fa * w.z; a.w += fa * w.w;
        b.x += fb * w.x; b.y += fb * w.y; b.z += fb * w.z; b.w += fb * w.w;
    }
    const size_t o = (size_t)row * INDIM + tid * 4;
    *reinterpret_cast<float4*>(outA + o) = a;
    *reinterpret_cast<float4*>(outB + o) = b;
}

// ---------------- launch ----------------------------------------------------
extern "C" void kernel_launch(void* const* d_in, const int* in_sizes, int n_in,
                              void* d_out, int out_size)
{
    const float* x_u     = (const float*)d_in[0];
    const float* x_c     = (const float*)d_in[1];
    const float* W_enc_u = (const float*)d_in[2];
    const float* b_enc_u = (const float*)d_in[3];
    const float* W_enc_c = (const float*)d_in[4];
    const float* b_enc_c = (const float*)d_in[5];
    const float* W_dec_u = (const float*)d_in[6];
    const float* W_dec_c = (const float*)d_in[7];

    float* out = (float*)d_out;
    const size_t ZN = (size_t)BATCH * DICT;
    const size_t XN = (size_t)BATCH * INDIM;
    float* z_u = out;
    float* z_c = out + ZN;
    float* mk  = out + 2 * ZN;
    float* xuh = out + 3 * ZN;
    float* xch = xuh + XN;
    float* xuc = xch + XN;
    float* xcc = xuc + XN;

    cudaFuncSetAttribute(gemm_bf16, cudaFuncAttributeMaxDynamicSharedMemorySize, GEMM_SMEM);

    conv_x<<<2048, 256>>>(x_u, 0);
    conv_x<<<2048, 256>>>(x_c, 1);
    trans_w<<<dim3(DICT / 32, INDIM / 32), dim3(32, 8)>>>(W_enc_u, 0);
    trans_w<<<dim3(DICT / 32, INDIM / 32), dim3(32, 8)>>>(W_enc_c, 1);

    // h~ staged in z_u / z_c output regions
    dim3 ggrid(BATCH / GBM, DICT / GBN);   // (32, 128), M fast
    gemm_bf16<<<ggrid, 256, GEMM_SMEM>>>(0, b_enc_u, z_u);
    gemm_bf16<<<ggrid, 256, GEMM_SMEM>>>(1, b_enc_c, z_c);

    topcand<<<BATCH, 256>>>(z_u, z_c);

    rescore<<<BATCH, 256>>>(x_u, x_c, b_enc_u, b_enc_c);

    fill_zero<<<8192, 256>>>((float4*)out, (3 * ZN) / 4);

    scatter_kernel<<<BATCH, MAXSEL>>>(z_u, z_c, mk);

    decode_kernel<<<BATCH, 256>>>(W_dec_u, xuh, xuc, 1);
    decode_kernel<<<BATCH, 256>>>(W_dec_c, xch, xcc, 0);
}

// round 5
// speedup vs baseline: 3.7011x; 1.1104x over previous
#include <cuda_runtime.h>
#include <cuda_bf16.h>
#include <cstdint>
#include <cstddef>

#define BATCH   4096
#define INDIM   1024
#define DICT    16384
#define KHALF   32
#define MAXSEL  64
#define CANDMAX 192
#define MARGIN  0.08f

// ---------------- __device__ scratch (no allocs) ----------------------------
__device__ __nv_bfloat16 g_xb [2][(size_t)BATCH * INDIM];
__device__ __nv_bfloat16 g_Wtb[2][(size_t)DICT * INDIM];   // W^T bf16 [N,K]
__device__ float         g_Wt [2][(size_t)DICT * INDIM];   // W^T fp32 [N,K]
__device__ __nv_bfloat16 g_hb [2][(size_t)BATCH * DICT];   // h~ bf16
__device__ int   g_cn [2][BATCH];
__device__ int   g_ci [2][BATCH][CANDMAX];
__device__ int   g_nsel[BATCH];
__device__ int   g_idx [BATCH * MAXSEL];
__device__ float g_hu  [BATCH * MAXSEL];
__device__ float g_hc  [BATCH * MAXSEL];

// ---------------- PTX helpers (sm_80-era only) -------------------------------
__device__ __forceinline__ uint32_t smem_u32(const void* p) {
    uint32_t a;
    asm("{ .reg .u64 t; cvta.to.shared.u64 t, %1; cvt.u32.u64 %0, t; }" : "=r"(a) : "l"(p));
    return a;
}
__device__ __forceinline__ void cpa16(uint32_t s, const void* g) {
    asm volatile("cp.async.cg.shared.global [%0], [%1], 16;" :: "r"(s), "l"(g));
}
__device__ __forceinline__ void cpa_commit() { asm volatile("cp.async.commit_group;" ::: "memory"); }
__device__ __forceinline__ void cpa_wait2()  { asm volatile("cp.async.wait_group 2;" ::: "memory"); }

__device__ __forceinline__ void ldsm4(uint32_t* r, uint32_t addr) {
    asm volatile("ldmatrix.sync.aligned.m8n8.x4.shared.b16 {%0,%1,%2,%3}, [%4];"
        : "=r"(r[0]), "=r"(r[1]), "=r"(r[2]), "=r"(r[3]) : "r"(addr));
}
__device__ __forceinline__ void mma16816(float* d, const uint32_t* a, const uint32_t* b) {
    asm volatile("mma.sync.aligned.m16n8k16.row.col.f32.bf16.bf16.f32 "
        "{%0,%1,%2,%3}, {%4,%5,%6,%7}, {%8,%9}, {%0,%1,%2,%3};"
        : "+f"(d[0]), "+f"(d[1]), "+f"(d[2]), "+f"(d[3])
        : "r"(a[0]), "r"(a[1]), "r"(a[2]), "r"(a[3]), "r"(b[0]), "r"(b[1]));
}

// ---------------- preprocessing ---------------------------------------------
__global__ void conv_x(const float* __restrict__ x, int enc)
{
    size_t n = (size_t)BATCH * INDIM;
    for (size_t i = (size_t)blockIdx.x * blockDim.x + threadIdx.x; i < n;
         i += (size_t)gridDim.x * blockDim.x)
        g_xb[enc][i] = __float2bfloat16_rn(x[i]);
}

// W [K,N] -> W^T fp32 + bf16 [N,K]
__global__ void trans_w(const float* __restrict__ W, int enc)
{
    __shared__ float t[32][33];
    const int n0 = blockIdx.x * 32, k0 = blockIdx.y * 32;
    const int tx = threadIdx.x, ty = threadIdx.y;
    #pragma unroll
    for (int j = 0; j < 4; j++)
        t[ty + j * 8][tx] = W[(size_t)(k0 + ty + j * 8) * DICT + n0 + tx];
    __syncthreads();
    #pragma unroll
    for (int j = 0; j < 4; j++) {
        float v = t[tx][ty + j * 8];
        size_t o = (size_t)(n0 + ty + j * 8) * INDIM + k0 + tx;
        g_Wt [enc][o] = v;
        g_Wtb[enc][o] = __float2bfloat16_rn(v);
    }
}

// ---------------- bf16 mma.sync GEMM (h~ out in bf16) ------------------------
#define GBM 128
#define GBN 128
#define GBK 32
#define GROWB 40
#define GSTB  20480
#define GST   3
#define GEMM_SMEM (GST * GSTB)
#define NKI (INDIM / GBK)

__device__ __forceinline__ void g_load(uint32_t sbase,
    const __nv_bfloat16* __restrict__ Xb, const __nv_bfloat16* __restrict__ Wb,
    int m0, int n0, int k0, int tid)
{
    #pragma unroll
    for (int r = 0; r < 2; r++) {
        int i = tid + r * 256;
        int row = i >> 2, c = i & 3;
        cpa16(sbase + row * 80 + c * 16,
              Xb + (size_t)(m0 + row) * INDIM + k0 + c * 8);
        cpa16(sbase + 10240 + row * 80 + c * 16,
              Wb + (size_t)(n0 + row) * INDIM + k0 + c * 8);
    }
}

__global__ void __launch_bounds__(256, 2)
gemm_bf16(int enc, const float* __restrict__ bias)
{
    extern __shared__ __align__(128) char sm[];
    __shared__ float s_bias[GBN];
    const uint32_t sb = smem_u32(sm);
    const int tid = threadIdx.x, lane = tid & 31, wid = tid >> 5;
    const int wm = wid & 1, wn = wid >> 1;
    const int m0 = blockIdx.x * GBM;
    const int n0 = blockIdx.y * GBN;

    const __nv_bfloat16* Xb = g_xb [enc];
    const __nv_bfloat16* Wb = g_Wtb[enc];
    __nv_bfloat16* C = g_hb[enc];

    if (tid < GBN) s_bias[tid] = bias[n0 + tid];

    #pragma unroll
    for (int p = 0; p < GST; p++) {
        g_load(sb + p * GSTB, Xb, Wb, m0, n0, p * GBK, tid);
        cpa_commit();
    }

    float acc[4][4][4];
    #pragma unroll
    for (int a = 0; a < 4; a++)
        #pragma unroll
        for (int b = 0; b < 4; b++)
            #pragma unroll
            for (int c = 0; c < 4; c++) acc[a][b][c] = 0.f;

    for (int t = 0; t < NKI; t++) {
        const int s = t - (t / 3) * 3;
        const uint32_t sA = sb + s * GSTB, sB = sA + 10240;

        cpa_wait2();
        __syncthreads();

        #pragma unroll
        for (int ks = 0; ks < GBK; ks += 16) {
            uint32_t af[4][4], bf[4][2];
            #pragma unroll
            for (int mi = 0; mi < 4; mi++) {
                uint32_t addr = sA +
                    ((wm * 64 + mi * 16 + (lane & 15)) * GROWB + ks + ((lane >> 4) << 3)) * 2;
                ldsm4(af[mi], addr);
            }
            #pragma unroll
            for (int h = 0; h < 2; h++) {
                uint32_t r[4];
                uint32_t addr = sB +
                    ((wn * 32 + h * 16 + (lane & 7) + ((lane >> 4) << 3)) * GROWB
                     + ks + (((lane >> 3) & 1) << 3)) * 2;
                ldsm4(r, addr);
                bf[h * 2][0] = r[0]; bf[h * 2][1] = r[1];
                bf[h * 2 + 1][0] = r[2]; bf[h * 2 + 1][1] = r[3];
            }
            #pragma unroll
            for (int mi = 0; mi < 4; mi++)
                #pragma unroll
                for (int ni = 0; ni < 4; ni++)
                    mma16816(acc[mi][ni], af[mi], bf[ni]);
        }
        __syncthreads();

        if (t + GST < NKI)
            g_load(sb + s * GSTB, Xb, Wb, m0, n0, (t + GST) * GBK, tid);
        cpa_commit();
    }

    #pragma unroll
    for (int mi = 0; mi < 4; mi++) {
        const int rbase = m0 + wm * 64 + mi * 16 + (lane >> 2);
        #pragma unroll
        for (int ni = 0; ni < 4; ni++) {
            const int col = n0 + wn * 32 + ni * 8 + (lane & 3) * 2;
            const float b0 = s_bias[col - n0], b1 = s_bias[col - n0 + 1];
            __nv_bfloat162 v0 = __float22bfloat162_rn(
                make_float2(acc[mi][ni][0] + b0, acc[mi][ni][1] + b1));
            __nv_bfloat162 v1 = __float22bfloat162_rn(
                make_float2(acc[mi][ni][2] + b0, acc[mi][ni][3] + b1));
            *reinterpret_cast<__nv_bfloat162*>(C + (size_t)rbase * DICT + col) = v0;
            *reinterpret_cast<__nv_bfloat162*>(C + (size_t)(rbase + 8) * DICT + col) = v1;
        }
    }
}

// ---------------- candidate selection (register-resident) --------------------
// One block per row. Each thread holds 64 bf16 of the row; 16-step binary
// search on the 16-bit monotone key space finds the 32nd-largest bf16 value;
// collect everything above (value32 - MARGIN).
__global__ void __launch_bounds__(256)
topcand()
{
    __shared__ int wcnt[8];
    __shared__ int s_cnt;
    const int row = blockIdx.x, tid = threadIdx.x;
    const int lane = tid & 31, wid = tid >> 5;

    for (int stream = 0; stream < 2; stream++) {
        const __nv_bfloat16* src = g_hb[stream] + (size_t)row * DICT;
        uint4 d[8];
        #pragma unroll
        for (int j = 0; j < 8; j++)
            d[j] = reinterpret_cast<const uint4*>(src)[tid + j * 256];

        unsigned lo = 0, hi = 0xFFFFu;
        #pragma unroll 1
        while (lo < hi) {
            const unsigned mid = (lo + hi + 1) >> 1;
            const unsigned short tb = (mid & 0x8000u)
                ? (unsigned short)(mid & 0x7FFFu)
                : (unsigned short)(~mid & 0xFFFFu);
            __nv_bfloat16_raw rr; rr.x = tb;
            const __nv_bfloat16 t1 = __nv_bfloat16(rr);
            const __nv_bfloat162 tv = __nv_bfloat162(t1, t1);

            __nv_bfloat162 accp = __nv_bfloat162(__float2bfloat16(0.f), __float2bfloat16(0.f));
            #pragma unroll
            for (int j = 0; j < 8; j++) {
                const __nv_bfloat162* p = reinterpret_cast<const __nv_bfloat162*>(&d[j]);
                #pragma unroll
                for (int q = 0; q < 4; q++)
                    accp = __hadd2(accp, __hge2(p[q], tv));
            }
            int c = (int)(__low2float(accp) + __high2float(accp));
            #pragma unroll
            for (int o = 16; o > 0; o >>= 1)
                c += __shfl_down_sync(0xFFFFFFFFu, c, o);
            if (lane == 0) wcnt[wid] = c;
            __syncthreads();
            if (tid == 0) {
                int tot = 0;
                #pragma unroll
                for (int w = 0; w < 8; w++) tot += wcnt[w];
                s_cnt = tot;
            }
            __syncthreads();
            if (s_cnt >= KHALF) lo = mid; else hi = mid - 1;
            __syncthreads();
        }

        // value of the 32nd-largest (lower bound), minus margin
        const unsigned short vb = (lo & 0x8000u)
            ? (unsigned short)(lo & 0x7FFFu)
            : (unsigned short)(~lo & 0xFFFFu);
        __nv_bfloat16_raw vr; vr.x = vb;
        const float cut = __bfloat162float(__nv_bfloat16(vr)) - MARGIN;

        if (tid == 0) s_cnt = 0;
        __syncthreads();
        #pragma unroll
        for (int j = 0; j < 8; j++) {
            const __nv_bfloat16* p = reinterpret_cast<const __nv_bfloat16*>(&d[j]);
            #pragma unroll
            for (int q = 0; q < 8; q++) {
                if (__bfloat162float(p[q]) > cut) {
                    int pos = atomicAdd(&s_cnt, 1);
                    if (pos < CANDMAX)
                        g_ci[stream][row][pos] = (tid + j * 256) * 8 + q;
                }
            }
        }
        __syncthreads();
        if (tid == 0) g_cn[stream][row] = s_cnt < CANDMAX ? s_cnt : CANDMAX;
        __syncthreads();
    }
}

// ---------------- exact rescore + selection ---------------------------------
__global__ void __launch_bounds__(256)
rescore(const float* __restrict__ xu, const float* __restrict__ xc,
        const float* __restrict__ bu, const float* __restrict__ bc)
{
    __shared__ float sxu[INDIM], sxc[INDIM];
    __shared__ int   ci[2][CANDMAX];
    __shared__ float chu[2][CANDMAX], chc[2][CANDMAX];
    __shared__ int   nc[2];
    __shared__ int   selidx[2][KHALF];
    __shared__ float selhu[2][KHALF], selhc[2][KHALF];
    __shared__ int   cnt;

    const int row = blockIdx.x, tid = threadIdx.x;
    const int lane = tid & 31, wid = tid >> 5;

    for (int i = tid; i < INDIM; i += 256) {
        sxu[i] = xu[(size_t)row * INDIM + i];
        sxc[i] = xc[(size_t)row * INDIM + i];
    }
    if (tid < 2) nc[tid] = g_cn[tid][row];
    __syncthreads();
    for (int s = 0; s < 2; s++)
        for (int t = tid; t < nc[s]; t += 256) ci[s][t] = g_ci[s][row][t];
    __syncthreads();

    const int tot = nc[0] + nc[1];
    for (int t = wid; t < tot; t += 8) {
        const int s  = (t < nc[0]) ? 0 : 1;
        const int tt = (s == 0) ? t : t - nc[0];
        const int j  = ci[s][tt];
        const float* wu = g_Wt[0] + (size_t)j * INDIM;
        const float* wc = g_Wt[1] + (size_t)j * INDIM;
        float su = 0.f, sc2 = 0.f;
        for (int i = lane; i < INDIM; i += 32) {
            su  += sxu[i] * __ldg(wu + i);
            sc2 += sxc[i] * __ldg(wc + i);
        }
        #pragma unroll
        for (int o = 16; o > 0; o >>= 1) {
            su  += __shfl_down_sync(0xFFFFFFFFu, su,  o);
            sc2 += __shfl_down_sync(0xFFFFFFFFu, sc2, o);
        }
        if (lane == 0) {
            chu[s][tt] = su  + bu[j];
            chc[s][tt] = sc2 + bc[j];
        }
    }
    __syncthreads();

    #pragma unroll
    for (int s = 0; s < 2; s++) {
        if (tid < nc[s]) {
            const float v = s ? chc[1][tid] : chu[0][tid];
            const int   j = ci[s][tid];
            int r = 0;
            for (int t2 = 0; t2 < nc[s]; t2++) {
                const float o = s ? chc[1][t2] : chu[0][t2];
                r += (o > v) || (o == v && ci[s][t2] < j);
            }
            if (r < KHALF) {
                selidx[s][r] = j;
                selhu[s][r]  = chu[s][tid];
                selhc[s][r]  = chc[s][tid];
            }
        }
    }
    __syncthreads();
    if (tid == 0) cnt = KHALF;
    __syncthreads();

    if (tid < KHALF) {
        g_idx[row * MAXSEL + tid] = selidx[0][tid];
        g_hu [row * MAXSEL + tid] = selhu[0][tid];
        g_hc [row * MAXSEL + tid] = selhc[0][tid];
    }
    if (tid < KHALF) {
        const int j = selidx[1][tid];
        bool dup = false;
        #pragma unroll
        for (int q = 0; q < KHALF; q++) dup |= (selidx[0][q] == j);
        if (!dup) {
            int p = atomicAdd(&cnt, 1);
            g_idx[row * MAXSEL + p] = j;
            g_hu [row * MAXSEL + p] = selhu[1][tid];
            g_hc [row * MAXSEL + p] = selhc[1][tid];
        }
    }
    __syncthreads();
    if (tid == 0) g_nsel[row] = cnt;
}

// ---------------- fill / scatter / decode -----------------------------------
__global__ void fill_zero(float4* __restrict__ p, size_t n4)
{
    size_t i = (size_t)blockIdx.x * blockDim.x + threadIdx.x;
    size_t stride = (size_t)gridDim.x * blockDim.x;
    float4 z = make_float4(0.f, 0.f, 0.f, 0.f);
    for (; i < n4; i += stride) p[i] = z;
}

__global__ void scatter_kernel(float* __restrict__ zu, float* __restrict__ zc,
                               float* __restrict__ mk)
{
    const int row = blockIdx.x;
    const int s   = threadIdx.x;
    if (s < g_nsel[row]) {
        const int idx = g_idx[row * MAXSEL + s];
        const size_t o = (size_t)row * DICT + idx;
        mk[o] = 1.0f;
        zu[o] = fmaxf(g_hu[row * MAXSEL + s], 0.f);
        zc[o] = fmaxf(g_hc[row * MAXSEL + s], 0.f);
    }
}

__global__ void __launch_bounds__(256)
decode_kernel(const float* __restrict__ Wd, float* __restrict__ outA,
              float* __restrict__ outB, int A_is_u)
{
    __shared__ int   sn;
    __shared__ int   sidx[MAXSEL];
    __shared__ float ca[MAXSEL], cb[MAXSEL];
    const int row = blockIdx.x;
    const int tid = threadIdx.x;

    if (tid == 0) sn = g_nsel[row];
    if (tid < MAXSEL) {
        sidx[tid] = g_idx[row * MAXSEL + tid];
        float zu = fmaxf(g_hu[row * MAXSEL + tid], 0.f);
        float zc = fmaxf(g_hc[row * MAXSEL + tid], 0.f);
        ca[tid] = A_is_u ? zu : zc;
        cb[tid] = A_is_u ? zc : zu;
    }
    __syncthreads();

    float4 a = make_float4(0.f, 0.f, 0.f, 0.f);
    float4 b = make_float4(0.f, 0.f, 0.f, 0.f);
    const int n = sn;
    #pragma unroll 4
    for (int s = 0; s < n; s++) {
        const float4 w = *reinterpret_cast<const float4*>(
            Wd + (size_t)sidx[s] * INDIM + tid * 4);
        const float fa = ca[s], fb = cb[s];
        a.x += fa * w.x; a.y += fa * w.y; a.z += fa * w.z; a.w += fa * w.w;
        b.x += fb * w.x; b.y += fb * w.y; b.z += fb * w.z; b.w += fb * w.w;
    }
    const size_t o = (size_t)row * INDIM + tid * 4;
    *reinterpret_cast<float4*>(outA + o) = a;
    *reinterpret_cast<float4*>(outB + o) = b;
}

// ---------------- launch ----------------------------------------------------
extern "C" void kernel_launch(void* const* d_in, const int* in_sizes, int n_in,
                              void* d_out, int out_size)
{
    const float* x_u     = (const float*)d_in[0];
    const float* x_c     = (const float*)d_in[1];
    const float* W_enc_u = (const float*)d_in[2];
    const float* b_enc_u = (const float*)d_in[3];
    const float* W_enc_c = (const float*)d_in[4];
    const float* b_enc_c = (const float*)d_in[5];
    const float* W_dec_u = (const float*)d_in[6];
    const float* W_dec_c = (const float*)d_in[7];

    float* out = (float*)d_out;
    const size_t ZN = (size_t)BATCH * DICT;
    const size_t XN = (size_t)BATCH * INDIM;
    float* z_u = out;
    float* z_c = out + ZN;
    float* mk  = out + 2 * ZN;
    float* xuh = out + 3 * ZN;
    float* xch = xuh + XN;
    float* xuc = xch + XN;
    float* xcc = xuc + XN;

    cudaFuncSetAttribute(gemm_bf16, cudaFuncAttributeMaxDynamicSharedMemorySize, GEMM_SMEM);

    conv_x<<<2048, 256>>>(x_u, 0);
    conv_x<<<2048, 256>>>(x_c, 1);
    trans_w<<<dim3(DICT / 32, INDIM / 32), dim3(32, 8)>>>(W_enc_u, 0);
    trans_w<<<dim3(DICT / 32, INDIM / 32), dim3(32, 8)>>>(W_enc_c, 1);

    dim3 ggrid(BATCH / GBM, DICT / GBN);
    gemm_bf16<<<ggrid, 256, GEMM_SMEM>>>(0, b_enc_u);
    gemm_bf16<<<ggrid, 256, GEMM_SMEM>>>(1, b_enc_c);

    topcand<<<BATCH, 256>>>();

    rescore<<<BATCH, 256>>>(x_u, x_c, b_enc_u, b_enc_c);

    fill_zero<<<8192, 256>>>((float4*)out, (3 * ZN) / 4);

    scatter_kernel<<<BATCH, MAXSEL>>>(z_u, z_c, mk);

    decode_kernel<<<BATCH, 256>>>(W_dec_u, xuh, xuc, 1);
    decode_kernel<<<BATCH, 256>>>(W_dec_c, xch, xcc, 0);
}